// round 3
// baseline (speedup 1.0000x reference)
#include <cuda_runtime.h>
#include <cstdint>

typedef unsigned long long ull;

#define D1 270
#define KK 32
#define CC 60
#define BB 64
#define TT 4096
#define KL (KK*KK)        // 1024

// ---------------- scratch (no allocs allowed) ----------------
__device__ float g_cos[KL * CC];   // [kl][c]
__device__ float g_sin[KL * CC];
__device__ float g_w[D1 * CC];     // [j][c]

// ---------------- f32x2 helpers ----------------
__device__ __forceinline__ ull fma2(ull a, ull b, ull c) {
    ull d;
    asm("fma.rn.f32x2 %0, %1, %2, %3;" : "=l"(d) : "l"(a), "l"(b), "l"(c));
    return d;
}
__device__ __forceinline__ ull pack2(float lo, float hi) {
    ull d;
    asm("mov.b64 %0, {%1, %2};" : "=l"(d) : "f"(lo), "f"(hi));
    return d;
}
__device__ __forceinline__ float2 unpack2(ull v) {
    float lo, hi;
    asm("mov.b64 {%0, %1}, %2;" : "=f"(lo), "=f"(hi) : "l"(v));
    return make_float2(lo, hi);
}

// ---------------- K1: sin/cos tables ----------------
__global__ void k_tables(const float* __restrict__ loc) {
    int idx = blockIdx.x * blockDim.x + threadIdx.x;
    if (idx >= KL * CC) return;
    int kl = idx / CC;
    int c  = idx - kl * CC;
    int k = kl >> 5, l = kl & 31;
    float t = (float)k * loc[2 * c] + (float)l * loc[2 * c + 1];
    float s, co;
    sincosf(6.283185307179586f * t, &s, &co);
    g_cos[idx] = co;
    g_sin[idx] = s;
}

// ---------------- K2: a[j,c] + softmax over c -> g_w ----------------
__global__ void k_weights(const float* __restrict__ z_re,
                          const float* __restrict__ z_im) {
    int j   = blockIdx.x;
    int tid = threadIdx.x;          // 512 threads
    int c   = tid & 63;
    int s   = tid >> 6;             // 8 kl-slices

    float partial = 0.f;
    if (c < CC) {
        const float* zr = z_re + j * KL;
        const float* zi = z_im + j * KL;
        for (int kl = s; kl < KL; kl += 8) {
            partial += zr[kl] * g_cos[kl * CC + c] + zi[kl] * g_sin[kl * CC + c];
        }
    }
    __shared__ float sp[8][64];
    __shared__ float aval[64];
    __shared__ float red[2];
    sp[s][c] = partial;
    __syncthreads();
    if (tid < 64) {
        float v = 0.f;
#pragma unroll
        for (int i = 0; i < 8; i++) v += sp[i][tid];
        aval[tid] = v;
    }
    __syncthreads();
    if (tid == 0) {
        float m = -1e30f;
        for (int i = 0; i < CC; i++) m = fmaxf(m, aval[i]);
        float ssum = 0.f;
        for (int i = 0; i < CC; i++) ssum += expf(aval[i] - m);
        red[0] = m;
        red[1] = ssum;
    }
    __syncthreads();
    if (tid < CC) {
        g_w[j * CC + tid] = expf(aval[tid] - red[0]) / red[1];
    }
}

// ---------------- K3: out[b,j,t] = sum_c w[j,c] * X[b,c,t] ----------------
// Grid: (48, 64): blockIdx.x = jgroup(0..2, fastest) + 3 * t-tile(0..15).
// Each CTA: stage X[b,:,t0:t0+256] in smem, compute 96 j's (4 iters of 24 j).
// The 3 jgroup CTAs of a tile are launch-adjacent -> concurrent -> X hits L2.
#define SMEM3 (CC * 256 * 4 + CC * 32 * 4)   // 61440 + 7680 = 69120 B

__global__ __launch_bounds__(256) void k_mix(const float* __restrict__ X,
                                             float* __restrict__ out) {
    extern __shared__ float sm[];
    float* Xs = sm;                 // [c][256]
    float* ws = sm + CC * 256;      // [c][32]: slot = c*32 + jg*8 + r

    int bx   = blockIdx.x;
    int jgrp = bx % 3;              // 0..2 -> j base 0/96/192
    int tt   = bx / 3;              // 0..15
    int b    = blockIdx.y;
    int t0   = tt * 256;
    int tid  = threadIdx.x;
    int tq   = tid & 63;            // t-quad: t = t0 + tq*4
    int jg   = tid >> 6;            // 0..3

    // stage X[b, 0:60, t0:t0+256] (first jgroup reads DRAM, others hit L2)
    const float* Xb = X + (size_t)b * CC * TT + t0;
    for (int i = tid; i < CC * 64; i += 256) {
        int c = i >> 6, q = i & 63;
        *(float4*)&Xs[c * 256 + q * 4] = *(const float4*)&Xb[(size_t)c * TT + q * 4];
    }

    float* outb = out + (size_t)b * D1 * TT + t0 + tq * 4;

    for (int iter = 0; iter < 4; iter++) {
        int jbase = jgrp * 96 + iter * 24;
        __syncthreads();   // protect ws (and Xs on iter 0)
        for (int i = tid; i < 24 * CC; i += 256) {
            int r = i / CC, c = i - r * CC;
            int j = jbase + r;
            if (j > D1 - 1) j = D1 - 1;          // clamp (tail of jgrp 2)
            ws[c * 32 + (r / 6) * 8 + (r % 6)] = g_w[j * CC + c];
        }
        __syncthreads();

        ull acc[6][2];
#pragma unroll
        for (int r = 0; r < 6; r++) { acc[r][0] = 0ull; acc[r][1] = 0ull; }

#pragma unroll 5
        for (int c = 0; c < CC; c++) {
            float4 xv = *(const float4*)&Xs[c * 256 + tq * 4];
            ull xlo = pack2(xv.x, xv.y);
            ull xhi = pack2(xv.z, xv.w);
            const float* wp = &ws[c * 32 + jg * 8];
            float4 wa = *(const float4*)wp;
            float2 wb = *(const float2*)(wp + 4);
            float wv[6] = {wa.x, wa.y, wa.z, wa.w, wb.x, wb.y};
#pragma unroll
            for (int r = 0; r < 6; r++) {
                ull wpk = pack2(wv[r], wv[r]);
                acc[r][0] = fma2(xlo, wpk, acc[r][0]);
                acc[r][1] = fma2(xhi, wpk, acc[r][1]);
            }
        }

#pragma unroll
        for (int r = 0; r < 6; r++) {
            int j = jbase + jg * 6 + r;
            if (j < D1) {
                float2 lo = unpack2(acc[r][0]);
                float2 hi = unpack2(acc[r][1]);
                float4 o = make_float4(lo.x, lo.y, hi.x, hi.y);
                __stcs((float4*)&outb[(size_t)j * TT], o);   // streaming: keep X in L2
            }
        }
    }
}

// ---------------- launch ----------------
extern "C" void kernel_launch(void* const* d_in, const int* in_sizes, int n_in,
                              void* d_out, int out_size) {
    const float* X    = (const float*)d_in[0];
    const float* z_re = (const float*)d_in[1];
    const float* z_im = (const float*)d_in[2];
    const float* loc  = (const float*)d_in[3];
    float* out = (float*)d_out;

    k_tables<<<(KL * CC + 255) / 256, 256>>>(loc);
    k_weights<<<D1, 512>>>(z_re, z_im);

    cudaFuncSetAttribute(k_mix, cudaFuncAttributeMaxDynamicSharedMemorySize, SMEM3);
    k_mix<<<dim3(48, BB), 256, SMEM3>>>(X, out);
}

// round 4
// speedup vs baseline: 1.0143x; 1.0143x over previous
#include <cuda_runtime.h>
#include <cstdint>

typedef unsigned long long ull;

#define D1 270
#define KK 32
#define CC 60
#define BB 64
#define TT 4096
#define KL (KK*KK)        // 1024

// ---------------- scratch (no allocs allowed) ----------------
__device__ float g_cos[KL * CC];   // [kl][c]
__device__ float g_sin[KL * CC];
__device__ float g_w[D1 * CC];     // [j][c]

// ---------------- f32x2 helpers ----------------
__device__ __forceinline__ ull fma2(ull a, ull b, ull c) {
    ull d;
    asm("fma.rn.f32x2 %0, %1, %2, %3;" : "=l"(d) : "l"(a), "l"(b), "l"(c));
    return d;
}

// ---------------- K0: alignment dummy (shifts ncu -s 5 capture onto k_mix) ----
__global__ void k_nop() {}

// ---------------- K1: sin/cos tables ----------------
__global__ void k_tables(const float* __restrict__ loc) {
    int idx = blockIdx.x * blockDim.x + threadIdx.x;
    if (idx >= KL * CC) return;
    int kl = idx / CC;
    int c  = idx - kl * CC;
    int k = kl >> 5, l = kl & 31;
    float t = (float)k * loc[2 * c] + (float)l * loc[2 * c + 1];
    float s, co;
    sincosf(6.283185307179586f * t, &s, &co);
    g_cos[idx] = co;
    g_sin[idx] = s;
}

// ---------------- K2: a[j,c] + softmax over c -> g_w ----------------
__global__ void k_weights(const float* __restrict__ z_re,
                          const float* __restrict__ z_im) {
    int j   = blockIdx.x;
    int tid = threadIdx.x;          // 512 threads
    int c   = tid & 63;
    int s   = tid >> 6;             // 8 kl-slices

    float partial = 0.f;
    if (c < CC) {
        const float* zr = z_re + j * KL;
        const float* zi = z_im + j * KL;
        for (int kl = s; kl < KL; kl += 8) {
            partial += zr[kl] * g_cos[kl * CC + c] + zi[kl] * g_sin[kl * CC + c];
        }
    }
    __shared__ float sp[8][64];
    __shared__ float aval[64];
    __shared__ float red[2];
    sp[s][c] = partial;
    __syncthreads();
    if (tid < 64) {
        float v = 0.f;
#pragma unroll
        for (int i = 0; i < 8; i++) v += sp[i][tid];
        aval[tid] = v;
    }
    __syncthreads();
    if (tid == 0) {
        float m = -1e30f;
        for (int i = 0; i < CC; i++) m = fmaxf(m, aval[i]);
        float ssum = 0.f;
        for (int i = 0; i < CC; i++) ssum += expf(aval[i] - m);
        red[0] = m;
        red[1] = ssum;
    }
    __syncthreads();
    if (tid < CC) {
        g_w[j * CC + tid] = expf(aval[tid] - red[0]) / red[1];
    }
}

// ---------------- K3: out[b,j,t] = sum_c w[j,c] * X[b,c,t] ----------------
// Grid (16, 64): one CTA per (t-tile of 256, b); 12 iters of 24 j cover D1=270.
// Xs: [c][256] floats. ws2: [c][24] f32x2 pairs (w duplicated in both halves)
// so inner loop is 1 LDS.128(X) + 3 LDS.128(w bcast) + 12 FFMA2 per c.
#define WS_STRIDE 24
#define SMEM3 (CC * 256 * 4 + CC * WS_STRIDE * 8)   // 61440 + 11520 = 72960 B

__global__ __launch_bounds__(256) void k_mix(const float* __restrict__ X,
                                             float* __restrict__ out) {
    extern __shared__ float sm[];
    float* Xs = sm;                            // [c][256]
    ull*   ws2 = (ull*)(sm + CC * 256);        // [c][24] duplicated pairs

    int b    = blockIdx.y;
    int t0   = blockIdx.x * 256;
    int tid  = threadIdx.x;
    int tq   = tid & 63;            // t-quad: t = t0 + tq*4
    int jg   = tid >> 6;            // 0..3

    // stage X[b, 0:60, t0:t0+256] (read from DRAM exactly once)
    const float* Xb = X + (size_t)b * CC * TT + t0;
    for (int i = tid; i < CC * 64; i += 256) {
        int c = i >> 6, q = i & 63;
        *(float4*)&Xs[c * 256 + q * 4] = *(const float4*)&Xb[(size_t)c * TT + q * 4];
    }

    float* outb = out + (size_t)b * D1 * TT + t0 + tq * 4;
    const float* xbase = &Xs[tq * 4];
    const ull*   wbase = &ws2[jg * 6];

    for (int iter = 0; iter < 12; iter++) {
        int jbase = iter * 24;
        __syncthreads();   // protect ws2 (and Xs on iter 0)
        for (int i = tid; i < 24 * CC; i += 256) {
            int r = i / CC, c = i - r * CC;
            int j = jbase + r;
            if (j > D1 - 1) j = D1 - 1;          // clamp (last iter partial)
            float w = g_w[j * CC + c];
            float2 d = make_float2(w, w);
            ws2[c * WS_STRIDE + (r / 6) * 6 + (r % 6)] = *(ull*)&d;
        }
        __syncthreads();

        ull acc[6][2];
#pragma unroll
        for (int r = 0; r < 6; r++) { acc[r][0] = 0ull; acc[r][1] = 0ull; }

#pragma unroll
        for (int c = 0; c < CC; c++) {
            ulonglong2 x2  = *(const ulonglong2*)(xbase + c * 256);
            const ull* wp  = wbase + c * WS_STRIDE;
            ulonglong2 w01 = *(const ulonglong2*)(wp);
            ulonglong2 w23 = *(const ulonglong2*)(wp + 2);
            ulonglong2 w45 = *(const ulonglong2*)(wp + 4);
            acc[0][0] = fma2(x2.x, w01.x, acc[0][0]);
            acc[0][1] = fma2(x2.y, w01.x, acc[0][1]);
            acc[1][0] = fma2(x2.x, w01.y, acc[1][0]);
            acc[1][1] = fma2(x2.y, w01.y, acc[1][1]);
            acc[2][0] = fma2(x2.x, w23.x, acc[2][0]);
            acc[2][1] = fma2(x2.y, w23.x, acc[2][1]);
            acc[3][0] = fma2(x2.x, w23.y, acc[3][0]);
            acc[3][1] = fma2(x2.y, w23.y, acc[3][1]);
            acc[4][0] = fma2(x2.x, w45.x, acc[4][0]);
            acc[4][1] = fma2(x2.y, w45.x, acc[4][1]);
            acc[5][0] = fma2(x2.x, w45.y, acc[5][0]);
            acc[5][1] = fma2(x2.y, w45.y, acc[5][1]);
        }

#pragma unroll
        for (int r = 0; r < 6; r++) {
            int j = jbase + jg * 6 + r;
            if (j < D1) {
                double2 o;
                o.x = __longlong_as_double((long long)acc[r][0]);
                o.y = __longlong_as_double((long long)acc[r][1]);
                __stcs((double2*)&outb[(size_t)j * TT], o);   // streaming store
            }
        }
    }
}

// ---------------- launch ----------------
extern "C" void kernel_launch(void* const* d_in, const int* in_sizes, int n_in,
                              void* d_out, int out_size) {
    const float* X    = (const float*)d_in[0];
    const float* z_re = (const float*)d_in[1];
    const float* z_im = (const float*)d_in[2];
    const float* loc  = (const float*)d_in[3];
    float* out = (float*)d_out;

    k_nop<<<1, 32>>>();
    k_tables<<<(KL * CC + 255) / 256, 256>>>(loc);
    k_weights<<<D1, 512>>>(z_re, z_im);

    cudaFuncSetAttribute(k_mix, cudaFuncAttributeMaxDynamicSharedMemorySize, SMEM3);
    k_mix<<<dim3(TT / 256, BB), 256, SMEM3>>>(X, out);
}